// round 4
// baseline (speedup 1.0000x reference)
#include <cuda_runtime.h>
#include <math.h>

#define VOCAB   50257
#define EMBED   128
#define HIDDEN  128
#define NCLASS  4
#define BB      256
#define TT      512
#define NTOK    (BB * TT)          // 131072

// x_proj scratch [t][b][h] : 64MB device global (no runtime alloc)
__device__ float g_xp[TT * BB * HIDDEN];

// ---------------------------------------------------------------- helpers
__device__ __forceinline__ unsigned smem_u32(const void* p) {
    return (unsigned)__cvta_generic_to_shared(p);
}
__device__ __forceinline__ void cp_async16(void* dst, const void* src) {
    asm volatile("cp.async.cg.shared.global [%0], [%1], 16;"
                 :: "r"(smem_u32(dst)), "l"(src));
}
__device__ __forceinline__ void cp_commit() {
    asm volatile("cp.async.commit_group;");
}
__device__ __forceinline__ void cp_wait1() {
    asm volatile("cp.async.wait_group 1;");
}
__device__ __forceinline__ void cp_wait0() {
    asm volatile("cp.async.wait_group 0;");
}
// packed dual fp32 FMA (sm_103a f32x2 pipe)
__device__ __forceinline__ unsigned long long
fma2(unsigned long long a, unsigned long long b, unsigned long long c) {
    unsigned long long d;
    asm("fma.rn.f32x2 %0, %1, %2, %3;" : "=l"(d) : "l"(a), "l"(b), "l"(c));
    return d;
}
__device__ __forceinline__ float2 unpack2(unsigned long long v) {
    float2 r;
    asm("mov.b64 {%0, %1}, %2;" : "=f"(r.x), "=f"(r.y) : "l"(v));
    return r;
}
__device__ __forceinline__ float fast_tanh(float x) {
    x = fminf(fmaxf(x, -15.0f), 15.0f);
    float e = __expf(2.0f * x);
    return 1.0f - __fdividef(2.0f, e + 1.0f);
}

// 64-float dot (one K-half) against 32 register ulonglong weight pairs.
// src: 16B-aligned shared, 64 floats = 16 ulonglong2.
__device__ __forceinline__ float dot64(
    const ulonglong2* __restrict__ src, const unsigned long long* __restrict__ w2)
{
    unsigned long long a0 = 0, a1 = 0, a2 = 0, a3 = 0;
    #pragma unroll
    for (int k = 0; k < 16; ++k) {
        ulonglong2 a = src[k];
        if (k & 1) {
            a2 = fma2(w2[2 * k],     a.x, a2);
            a3 = fma2(w2[2 * k + 1], a.y, a3);
        } else {
            a0 = fma2(w2[2 * k],     a.x, a0);
            a1 = fma2(w2[2 * k + 1], a.y, a1);
        }
    }
    float2 u0 = unpack2(a0), u1 = unpack2(a1);
    float2 u2 = unpack2(a2), u3 = unpack2(a3);
    return ((u0.x + u0.y) + (u1.x + u1.y)) + ((u2.x + u2.y) + (u3.x + u3.y));
}

// ---------------------------------------------------------------------------
// Kernel 1: x_proj = emb[x] @ W_ih^T + (b_ih + b_hh)
// 148 CTAs x 512 threads. Thread = (out = tid&127, sec = tid>>8 K-half,
// sub = (tid>>7)&1 token-slot group). 64 weight floats in regs per thread.
// Embeddings staged 16 tokens/chunk via cp.async (double buffered); K-half
// partials combined through shared.
// ---------------------------------------------------------------------------
#define XP_GRID  148
#define XP_TPC   886            // tokens per CTA (148*886 >= 131072)
#define XP_CH    16
#define XP_NC    ((XP_TPC + XP_CH - 1) / XP_CH)   // 56

// shared layout (floats): ids[896] | act[2][2048] | part[2048]
#define XPS_IDS   0
#define XPS_ACT   896
#define XPS_PART  (896 + 4096)
#define XPS_TOT   (896 + 4096 + 2048)

__global__ void __launch_bounds__(512, 1) xproj_kernel(
    const int* __restrict__ x, const float* __restrict__ emb,
    const float* __restrict__ W_ih, const float* __restrict__ b_ih,
    const float* __restrict__ b_hh)
{
    extern __shared__ float sh[];
    int*   s_ids  = (int*)(sh + XPS_IDS);
    float* s_act  = sh + XPS_ACT;
    float* s_part = sh + XPS_PART;

    const int tid = threadIdx.x;
    const int out = tid & 127;
    const int sub = (tid >> 7) & 1;
    const int sec = tid >> 8;
    const int r0  = blockIdx.x * XP_TPC;

    // stage token ids (pad with 0 -> emb pad row is zero)
    for (int i = tid; i < 896; i += 512) {
        int r = r0 + i;
        s_ids[i] = (i < XP_TPC && r < NTOK) ? x[r] : 0;
    }

    // stage W_ih half-rows into registers (4 coalesced passes via s_act region)
    unsigned long long w2[32];
    for (int p = 0; p < 4; ++p) {
        for (int i = tid; i < 4096; i += 512)
            s_act[i] = W_ih[p * 4096 + i];
        __syncthreads();
        if ((out >> 5) == p) {
            const unsigned long long* row = (const unsigned long long*)
                (s_act + (out & 31) * 128 + sec * 64);
            #pragma unroll
            for (int k = 0; k < 32; ++k) w2[k] = row[k];
        }
        __syncthreads();
    }
    const float bias = b_ih[out] + b_hh[out];

    // prologue: stage chunk 0 (512 threads x 16B = 16 tokens x 128 floats)
    {
        int slot = tid >> 5, k4 = tid & 31;
        int id = s_ids[slot];
        cp_async16(s_act + slot * 128 + k4 * 4,
                   emb + (size_t)id * EMBED + k4 * 4);
        cp_commit();
    }

    for (int c = 0; c < XP_NC; ++c) {
        if (c + 1 < XP_NC) {
            float* dst = s_act + ((c + 1) & 1) * 2048;
            int slot = tid >> 5, k4 = tid & 31;
            int id = s_ids[(c + 1) * XP_CH + slot];
            cp_async16(dst + slot * 128 + k4 * 4,
                       emb + (size_t)id * EMBED + k4 * 4);
            cp_commit();
            cp_wait1();
        } else {
            cp_wait0();
        }
        __syncthreads();   // bar1: staged data ready; prev finalize done

        const float* buf = s_act + (c & 1) * 2048;
        float dots[8];
        #pragma unroll
        for (int j = 0; j < 8; ++j) {
            int slot = sub * 8 + j;
            dots[j] = dot64(
                (const ulonglong2*)(buf + slot * 128 + sec * 64), w2);
            if (sec == 1)
                s_part[slot * 128 + out] = dots[j];
        }
        __syncthreads();   // bar2: partials visible

        if (sec == 0) {
            #pragma unroll
            for (int j = 0; j < 8; ++j) {
                int slot = sub * 8 + j;
                int i_tok = c * XP_CH + slot;
                int r = r0 + i_tok;
                if (i_tok < XP_TPC && r < NTOK) {
                    float s = dots[j] + s_part[slot * 128 + out] + bias;
                    int b = r >> 9, t = r & (TT - 1);
                    g_xp[((size_t)t * BB + b) * HIDDEN + out] = s;
                }
            }
        }
        // next iteration's bar1 protects s_part from early overwrite
    }
}

// ---------------------------------------------------------------------------
// Kernel 2: recurrence. 128 CTAs x 512 threads (1 CTA/SM, 4 warps/SMSP).
// Thread = (row = (tid>>7)&1, out = tid&127, sec = tid>>8 K-half).
// W_hh half-rows register-resident. h double-buffered in shared; K-half
// partial reduced through shared; 2 bars/step. xp prefetched 2 steps ahead.
// ---------------------------------------------------------------------------
// shared layout (floats): h[2][256] | part[256] | stage[4096]
#define RNS_H     0
#define RNS_PART  512
#define RNS_STG   768
#define RNS_TOT   (768 + 4096)

__global__ void __launch_bounds__(512, 1) rnn_kernel(
    const float* __restrict__ h0, const float* __restrict__ W_hh,
    float* __restrict__ out_hidden)
{
    extern __shared__ float sh[];
    float* s_h    = sh + RNS_H;
    float* s_part = sh + RNS_PART;
    float* s_stg  = sh + RNS_STG;

    const int tid = threadIdx.x;
    const int out = tid & 127;
    const int row = (tid >> 7) & 1;
    const int sec = tid >> 8;
    const int b   = blockIdx.x * 2 + row;

    // stage W_hh half-rows -> registers
    unsigned long long w2[32];
    for (int p = 0; p < 4; ++p) {
        for (int i = tid; i < 4096; i += 512)
            s_stg[i] = W_hh[p * 4096 + i];
        __syncthreads();
        if ((out >> 5) == p) {
            const unsigned long long* wrow = (const unsigned long long*)
                (s_stg + (out & 31) * 128 + sec * 64);
            #pragma unroll
            for (int k = 0; k < 32; ++k) w2[k] = wrow[k];
        }
        __syncthreads();
    }

    if (sec == 0)
        s_h[row * 128 + out] = h0[(size_t)b * HIDDEN + out];
    __syncthreads();

    const float* xp_me = g_xp + (size_t)b * HIDDEN + out;
    float xv0 = 0.f, xv1 = 0.f;
    if (sec == 0) {
        xv0 = __ldg(xp_me);
        xv1 = __ldg(xp_me + (size_t)(BB * HIDDEN));
    }
    float h = 0.0f;

    for (int t = 0; t < TT; ++t) {
        float xv2 = 0.f;
        if (sec == 0 && t + 2 < TT)
            xv2 = __ldg(xp_me + (size_t)(t + 2) * (BB * HIDDEN));

        const ulonglong2* h4 = (const ulonglong2*)
            (s_h + (t & 1) * 256 + row * 128 + sec * 64);
        float d = dot64(h4, w2);

        if (sec == 1)
            s_part[row * 128 + out] = d;
        __syncthreads();   // bar1: partial visible

        if (sec == 0) {
            float s = d + s_part[row * 128 + out] + xv0;
            h = fast_tanh(s);
            s_h[((t + 1) & 1) * 256 + row * 128 + out] = h;
            xv0 = xv1; xv1 = xv2;
        }
        __syncthreads();   // bar2: new h visible; part consumed
    }

    if (sec == 0)
        out_hidden[(size_t)b * HIDDEN + out] = h;
}

// ---------------------------------------------------------------------------
// Kernel 3: MLP head. One CTA per batch row.
// ---------------------------------------------------------------------------
__global__ void __launch_bounds__(256) head_kernel(
    const float* __restrict__ hidden, const float* __restrict__ W1,
    const float* __restrict__ b1, const float* __restrict__ W2,
    const float* __restrict__ b2, float* __restrict__ logits)
{
    __shared__ float shH[HIDDEN];
    __shared__ float shM[2 * HIDDEN];
    const int b = blockIdx.x, tid = threadIdx.x;
    if (tid < HIDDEN) shH[tid] = hidden[(size_t)b * HIDDEN + tid];
    __syncthreads();

    float acc = b1[tid];
    const float4* w4 = (const float4*)(W1 + (size_t)tid * HIDDEN);
    const float4* h4 = (const float4*)shH;
    #pragma unroll 8
    for (int k4 = 0; k4 < 32; ++k4) {
        float4 w = w4[k4];
        float4 h = h4[k4];
        acc = fmaf(w.x, h.x, acc);
        acc = fmaf(w.y, h.y, acc);
        acc = fmaf(w.z, h.z, acc);
        acc = fmaf(w.w, h.w, acc);
    }
    shM[tid] = fmaxf(acc, 0.0f);
    __syncthreads();

    if (tid < NCLASS) {
        float a = b2[tid];
        const float* w2 = W2 + (size_t)tid * (2 * HIDDEN);
        #pragma unroll 8
        for (int k = 0; k < 2 * HIDDEN; ++k)
            a = fmaf(shM[k], w2[k], a);
        logits[(size_t)b * NCLASS + tid] = a;
    }
}

// ---------------------------------------------------------------------------
extern "C" void kernel_launch(void* const* d_in, const int* in_sizes, int n_in,
                              void* d_out, int out_size)
{
    const int*   x    = (const int*)  d_in[0];
    const float* h0   = (const float*)d_in[1];
    const float* emb  = (const float*)d_in[2];
    const float* W_ih = (const float*)d_in[3];
    const float* W_hh = (const float*)d_in[4];
    const float* b_ih = (const float*)d_in[5];
    const float* b_hh = (const float*)d_in[6];
    const float* W1   = (const float*)d_in[7];
    const float* b1   = (const float*)d_in[8];
    const float* W2   = (const float*)d_in[9];
    const float* b2   = (const float*)d_in[10];

    float* out    = (float*)d_out;
    float* logits = out;                 // [256*4]
    float* hidden = out + BB * NCLASS;   // [256*128]

    const int smem1 = XPS_TOT * sizeof(float);   // ~28KB
    const int smem2 = RNS_TOT * sizeof(float);   // ~19KB

    xproj_kernel<<<XP_GRID, 512, smem1>>>(x, emb, W_ih, b_ih, b_hh);
    rnn_kernel<<<BB / 2, 512, smem2>>>(h0, W_hh, hidden);
    head_kernel<<<BB, 256>>>(hidden, W1, b1, W2, b2, logits);
}